// round 1
// baseline (speedup 1.0000x reference)
#include <cuda_runtime.h>

#define HID 96
#define CIN 192
#define MAXN 120000
#define EPSBN 1e-5f

#define TM 128
#define KC 16
#define NCH (CIN / KC)   // 12 chunks of 16

// ---- scratch (static device globals; no allocation) ----
__device__ float g_vsum[(size_t)(MAXN + 1) * CIN];   // vsum -> vpad (row M = zeros)
__device__ float g_cnt[MAXN];
__device__ float g_acc[(size_t)MAXN * HID];          // conv output
__device__ float g_ypad[(size_t)(MAXN + 1) * HID];   // BN+ReLU output, padded
__device__ float g_bn[2 * HID];                      // [0:96) sum, [96:192) sumsq
__device__ float g_ss[2 * HID];                      // [0:96) scale, [96:192) shift

// ---- 1: concat + scatter-add (mean numerator) ----
__global__ void scatter_kernel(const float* __restrict__ hF, const float* __restrict__ qF,
                               const int* __restrict__ seg, int N) {
    long long t = (long long)blockIdx.x * blockDim.x + threadIdx.x;
    if (t >= (long long)N * CIN) return;
    int n = (int)(t / CIN);
    int c = (int)(t - (long long)n * CIN);
    float v = (c < HID) ? hF[(size_t)n * HID + c] : qF[(size_t)n * HID + (c - HID)];
    int m = seg[n];
    atomicAdd(&g_vsum[(size_t)m * CIN + c], v);
    if (c == 0) atomicAdd(&g_cnt[m], 1.0f);
}

// ---- 2: divide by count -> vfeat (in place) ----
__global__ void normalize_kernel(int M) {
    long long t = (long long)blockIdx.x * blockDim.x + threadIdx.x;
    if (t >= (long long)M * CIN) return;
    int m = (int)(t / CIN);
    float ct = g_cnt[m];
    if (ct < 1.0f) ct = 1.0f;
    g_vsum[t] = g_vsum[t] / ct;
}

// ---- 3: sparse 3x3x3 conv as gathered GEMM ----
// acc[m][j] = sum_k sum_c vpad[nbr[m][k]][c] * W[k][c][j]
__global__ __launch_bounds__(256, 2)
void conv_kernel(const float* __restrict__ W, const int* __restrict__ nbr, int M) {
    __shared__ float As[2][TM * (KC + 1)];
    __shared__ float Bs[2][KC * HID];
    __shared__ int nrow[TM];

    const float* __restrict__ vpad = g_vsum;
    int tid = threadIdx.x;
    int mbase = blockIdx.x * TM;
    int tr = tid >> 4;   // 0..15 -> rows tr*8 .. tr*8+7
    int tc = tid & 15;   // 0..15 -> cols tc*6 .. tc*6+5

    float acc[8][6];
#pragma unroll
    for (int i = 0; i < 8; ++i)
#pragma unroll
        for (int p = 0; p < 6; ++p) acc[i][p] = 0.0f;

    for (int k = 0; k < 27; ++k) {
        if (tid < TM) {
            int m = mbase + tid;
            nrow[tid] = (m < M) ? nbr[(size_t)m * 27 + k] : M;  // row M = zero pad
        }
        __syncthreads();
        // load chunk 0 into buffer 0
        {
#pragma unroll
            for (int i = 0; i < 8; ++i) {           // 2048 A elems
                int idx = i * 256 + tid;
                int c = idx & (KC - 1), r = idx >> 4;
                As[0][r * (KC + 1) + c] = vpad[(size_t)nrow[r] * CIN + c];
            }
#pragma unroll
            for (int i = 0; i < 6; ++i) {           // 1536 B elems
                int idx = i * 256 + tid;
                Bs[0][idx] = W[(size_t)k * CIN * HID + idx];
            }
        }
        __syncthreads();
        int buf = 0;
#pragma unroll
        for (int ch = 0; ch < NCH; ++ch) {
            float ra[8], rb[6];
            if (ch < NCH - 1) {
                int cbase = (ch + 1) * KC;
#pragma unroll
                for (int i = 0; i < 8; ++i) {
                    int idx = i * 256 + tid;
                    int c = idx & (KC - 1), r = idx >> 4;
                    ra[i] = vpad[(size_t)nrow[r] * CIN + cbase + c];
                }
#pragma unroll
                for (int i = 0; i < 6; ++i) {
                    int idx = i * 256 + tid;
                    rb[i] = W[(size_t)k * CIN * HID + (size_t)cbase * HID + idx];
                }
            }
            const float* Ab = &As[buf][0];
            const float* Bb = &Bs[buf][0];
#pragma unroll
            for (int c = 0; c < KC; ++c) {
                float a[8], b[6];
#pragma unroll
                for (int i = 0; i < 8; ++i) a[i] = Ab[(tr * 8 + i) * (KC + 1) + c];
#pragma unroll
                for (int p = 0; p < 6; ++p) b[p] = Bb[c * HID + tc * 6 + p];
#pragma unroll
                for (int i = 0; i < 8; ++i)
#pragma unroll
                    for (int p = 0; p < 6; ++p) acc[i][p] += a[i] * b[p];
            }
            if (ch < NCH - 1) {
                int nb = buf ^ 1;
#pragma unroll
                for (int i = 0; i < 8; ++i) {
                    int idx = i * 256 + tid;
                    int c = idx & (KC - 1), r = idx >> 4;
                    As[nb][r * (KC + 1) + c] = ra[i];
                }
#pragma unroll
                for (int i = 0; i < 6; ++i) Bs[nb][i * 256 + tid] = rb[i];
                __syncthreads();
                buf = nb;
            }
        }
    }
#pragma unroll
    for (int i = 0; i < 8; ++i) {
        int m = mbase + tr * 8 + i;
        if (m < M) {
#pragma unroll
            for (int p = 0; p < 6; ++p)
                g_acc[(size_t)m * HID + tc * 6 + p] = acc[i][p];
        }
    }
}

// ---- 4: BN statistics (partial sums -> atomics) ----
__global__ void bnstats_kernel(int M) {
    int j = threadIdx.x % HID;
    int rs = threadIdx.x / HID;   // 0..3
    float s = 0.0f, q = 0.0f;
    for (int r = blockIdx.x * 4 + rs; r < M; r += gridDim.x * 4) {
        float v = g_acc[(size_t)r * HID + j];
        s += v;
        q += v * v;
    }
    __shared__ float sh[2][384];
    sh[0][threadIdx.x] = s;
    sh[1][threadIdx.x] = q;
    __syncthreads();
    if (threadIdx.x < HID) {
        s = sh[0][j] + sh[0][j + 96] + sh[0][j + 192] + sh[0][j + 288];
        q = sh[1][j] + sh[1][j + 96] + sh[1][j + 192] + sh[1][j + 288];
        atomicAdd(&g_bn[j], s);
        atomicAdd(&g_bn[HID + j], q);
    }
}

// ---- 5: BN scale/shift ----
__global__ void bnscale_kernel(const float* __restrict__ gamma,
                               const float* __restrict__ beta, int M) {
    int j = threadIdx.x;
    if (j >= HID) return;
    float inv = 1.0f / (float)M;
    float mu = g_bn[j] * inv;
    float var = g_bn[HID + j] * inv - mu * mu;
    if (var < 0.0f) var = 0.0f;
    float sc = gamma[j] * rsqrtf(var + EPSBN);
    g_ss[j] = sc;
    g_ss[HID + j] = beta[j] - mu * sc;
}

// ---- 6: BN apply + ReLU -> ypad (row M zero) ----
__global__ void ypad_kernel(int M) {
    long long t = (long long)blockIdx.x * blockDim.x + threadIdx.x;
    if (t >= (long long)(M + 1) * HID) return;
    int m = (int)(t / HID);
    int j = (int)(t - (long long)m * HID);
    float v = 0.0f;
    if (m < M) {
        v = g_acc[t] * g_ss[j] + g_ss[HID + j];
        v = v > 0.0f ? v : 0.0f;
    }
    g_ypad[t] = v;
}

// ---- 7: residual linear GEMM: out = hx @ W_lin + b_lin ----
__global__ __launch_bounds__(256, 2)
void linear_kernel(const float* __restrict__ hF, const float* __restrict__ qF,
                   const float* __restrict__ Wl, const float* __restrict__ bl,
                   float* __restrict__ out, int N) {
    __shared__ float As[2][TM * (KC + 1)];
    __shared__ float Bs[2][KC * HID];

    int tid = threadIdx.x;
    int nbase = blockIdx.x * TM;
    int tr = tid >> 4;
    int tc = tid & 15;

    float acc[8][6];
#pragma unroll
    for (int i = 0; i < 8; ++i)
#pragma unroll
        for (int p = 0; p < 6; ++p) acc[i][p] = 0.0f;

    // chunk 0
    {
#pragma unroll
        for (int i = 0; i < 8; ++i) {
            int idx = i * 256 + tid;
            int c = idx & (KC - 1), r = idx >> 4;
            int n = nbase + r;
            float v = 0.0f;
            if (n < N) v = hF[(size_t)n * HID + c];  // cbase=0 < 96
            As[0][r * (KC + 1) + c] = v;
        }
#pragma unroll
        for (int i = 0; i < 6; ++i) {
            int idx = i * 256 + tid;
            Bs[0][idx] = Wl[idx];
        }
    }
    __syncthreads();
    int buf = 0;
#pragma unroll
    for (int ch = 0; ch < NCH; ++ch) {
        float ra[8], rb[6];
        if (ch < NCH - 1) {
            int cbase = (ch + 1) * KC;
#pragma unroll
            for (int i = 0; i < 8; ++i) {
                int idx = i * 256 + tid;
                int c = idx & (KC - 1), r = idx >> 4;
                int n = nbase + r;
                int col = cbase + c;
                float v = 0.0f;
                if (n < N)
                    v = (col < HID) ? hF[(size_t)n * HID + col]
                                    : qF[(size_t)n * HID + (col - HID)];
                ra[i] = v;
            }
#pragma unroll
            for (int i = 0; i < 6; ++i) {
                int idx = i * 256 + tid;
                rb[i] = Wl[(size_t)cbase * HID + idx];
            }
        }
        const float* Ab = &As[buf][0];
        const float* Bb = &Bs[buf][0];
#pragma unroll
        for (int c = 0; c < KC; ++c) {
            float a[8], b[6];
#pragma unroll
            for (int i = 0; i < 8; ++i) a[i] = Ab[(tr * 8 + i) * (KC + 1) + c];
#pragma unroll
            for (int p = 0; p < 6; ++p) b[p] = Bb[c * HID + tc * 6 + p];
#pragma unroll
            for (int i = 0; i < 8; ++i)
#pragma unroll
                for (int p = 0; p < 6; ++p) acc[i][p] += a[i] * b[p];
        }
        if (ch < NCH - 1) {
            int nb = buf ^ 1;
#pragma unroll
            for (int i = 0; i < 8; ++i) {
                int idx = i * 256 + tid;
                int c = idx & (KC - 1), r = idx >> 4;
                As[nb][r * (KC + 1) + c] = ra[i];
            }
#pragma unroll
            for (int i = 0; i < 6; ++i) Bs[nb][i * 256 + tid] = rb[i];
            __syncthreads();
            buf = nb;
        }
    }
#pragma unroll
    for (int i = 0; i < 8; ++i) {
        int n = nbase + tr * 8 + i;
        if (n < N) {
#pragma unroll
            for (int p = 0; p < 6; ++p)
                out[(size_t)n * HID + tc * 6 + p] = acc[i][p] + bl[tc * 6 + p];
        }
    }
}

// ---- 8: trilinear 8-corner gather, accumulate into out ----
__global__ void trilinear_kernel(const float* __restrict__ cw, const int* __restrict__ cidx,
                                 float* __restrict__ out, int N) {
    long long t = (long long)blockIdx.x * blockDim.x + threadIdx.x;
    if (t >= (long long)N * HID) return;
    int n = (int)(t / HID);
    int j = (int)(t - (long long)n * HID);
    float s = out[t];
#pragma unroll
    for (int k = 0; k < 8; ++k) {
        int ci = cidx[(size_t)n * 8 + k];
        float w = cw[(size_t)n * 8 + k];
        s += w * g_ypad[(size_t)ci * HID + j];
    }
    out[t] = s;
}

extern "C" void kernel_launch(void* const* d_in, const int* in_sizes, int n_in,
                              void* d_out, int out_size) {
    const float* hF    = (const float*)d_in[0];
    const float* qF    = (const float*)d_in[1];
    const float* Wc    = (const float*)d_in[2];
    const float* gamma = (const float*)d_in[3];
    const float* beta  = (const float*)d_in[4];
    const float* Wl    = (const float*)d_in[5];
    const float* bl    = (const float*)d_in[6];
    const float* cw    = (const float*)d_in[7];
    const int*   seg   = (const int*)d_in[8];
    const int*   nbr   = (const int*)d_in[9];
    const int*   cidx  = (const int*)d_in[10];
    float* out = (float*)d_out;

    int N = in_sizes[8];
    int M = in_sizes[9] / 27;

    void *pv, *pc, *pb;
    cudaGetSymbolAddress(&pv, g_vsum);
    cudaGetSymbolAddress(&pc, g_cnt);
    cudaGetSymbolAddress(&pb, g_bn);
    cudaMemsetAsync(pv, 0, (size_t)(M + 1) * CIN * sizeof(float), 0);
    cudaMemsetAsync(pc, 0, (size_t)M * sizeof(float), 0);
    cudaMemsetAsync(pb, 0, 2 * HID * sizeof(float), 0);

    long long nt;

    nt = (long long)N * CIN;
    scatter_kernel<<<(unsigned)((nt + 255) / 256), 256>>>(hF, qF, seg, N);

    nt = (long long)M * CIN;
    normalize_kernel<<<(unsigned)((nt + 255) / 256), 256>>>(M);

    conv_kernel<<<(M + TM - 1) / TM, 256>>>(Wc, nbr, M);

    bnstats_kernel<<<512, 384>>>(M);
    bnscale_kernel<<<1, HID>>>(gamma, beta, M);

    nt = (long long)(M + 1) * HID;
    ypad_kernel<<<(unsigned)((nt + 255) / 256), 256>>>(M);

    linear_kernel<<<(N + TM - 1) / TM, 256>>>(hF, qF, Wl, bl, out, N);

    nt = (long long)N * HID;
    trilinear_kernel<<<(unsigned)((nt + 255) / 256), 256>>>(cw, cidx, out, N);
}

// round 3
// speedup vs baseline: 2.1941x; 2.1941x over previous
#include <cuda_runtime.h>
#include <cuda_bf16.h>
#include <cstdint>

#define HID 96
#define CIN 192
#define MAXN 120000
#define EPSBN 1e-5f

// fp32 linear GEMM params
#define TM 128
#define KC 16
#define NCH (CIN / KC)

// ===== conv mma params =====
#define CTM 128                        // voxel rows per CTA
#define NSTG 162                       // 27 offsets * 6 chunks of K=32
#define ASTRIDE 80                     // bytes per A/B smem row (32 bf16 + 8 pad)
#define APLANE (128 * ASTRIDE)         // 10240 B
#define BPLANE (96 * ASTRIDE)          // 7680 B
#define STGB (2 * APLANE + 2 * BPLANE) // 35840 B
#define SMEM_CONV (2 * STGB)           // 71680 B

// ---- scratch (static device globals; no allocation) ----
__device__ float g_vsum[(size_t)(MAXN + 1) * CIN];   // vsum -> vpad (row M = zeros)
__device__ float g_cnt[MAXN];
__device__ float g_acc[(size_t)MAXN * HID];          // conv output
__device__ float g_ypad[(size_t)(MAXN + 1) * HID];   // BN+ReLU output, padded
__device__ float g_bn[2 * HID];
__device__ float g_ss[2 * HID];
// pre-split weights, bf16, per stage: [hi|lo][n=96][k=32] compact
__device__ __nv_bfloat16 g_wprep[(size_t)NSTG * 2 * 96 * 32];

__device__ __forceinline__ uint32_t pack_bf16(float x, float y) {
    __nv_bfloat162 t = __floats2bfloat162_rn(x, y);
    return *reinterpret_cast<uint32_t*>(&t);
}

#define MMA_BF16(d, a, b)                                                     \
    asm volatile(                                                             \
        "mma.sync.aligned.m16n8k16.row.col.f32.bf16.bf16.f32 "               \
        "{%0,%1,%2,%3},{%4,%5,%6,%7},{%8,%9},{%0,%1,%2,%3};"                 \
        : "+f"((d)[0]), "+f"((d)[1]), "+f"((d)[2]), "+f"((d)[3])              \
        : "r"((a)[0]), "r"((a)[1]), "r"((a)[2]), "r"((a)[3]),                 \
          "r"((b)[0]), "r"((b)[1]))

// ---- 0: weight prep: transpose + bf16 hi/lo split ----
// stage b = k*6 + ch; output [2][96][32] bf16 per stage, n-major (k contiguous)
__global__ void prep_kernel(const float* __restrict__ W) {
    int b = blockIdx.x;
    int k = b / 6, ch = b - k * 6;
    __nv_bfloat16* dst = g_wprep + (size_t)b * 2 * 3072;
    for (int idx = threadIdx.x; idx < 3072; idx += blockDim.x) {
        int n = idx >> 5;      // 0..95 output channel
        int c = idx & 31;      // k within chunk
        float w = W[((size_t)k * CIN + (ch * 32 + c)) * HID + n];
        float hi = __bfloat162float(__float2bfloat16(w));
        dst[idx] = __float2bfloat16(hi);
        dst[3072 + idx] = __float2bfloat16(w - hi);
    }
}

// ---- 1: concat + scatter-add ----
__global__ void scatter_kernel(const float* __restrict__ hF, const float* __restrict__ qF,
                               const int* __restrict__ seg, int N) {
    long long t = (long long)blockIdx.x * blockDim.x + threadIdx.x;
    if (t >= (long long)N * CIN) return;
    int n = (int)(t / CIN);
    int c = (int)(t - (long long)n * CIN);
    float v = (c < HID) ? hF[(size_t)n * HID + c] : qF[(size_t)n * HID + (c - HID)];
    int m = seg[n];
    atomicAdd(&g_vsum[(size_t)m * CIN + c], v);
    if (c == 0) atomicAdd(&g_cnt[m], 1.0f);
}

// ---- 2: divide by count ----
__global__ void normalize_kernel(int M) {
    long long t = (long long)blockIdx.x * blockDim.x + threadIdx.x;
    if (t >= (long long)M * CIN) return;
    int m = (int)(t / CIN);
    float ct = g_cnt[m];
    if (ct < 1.0f) ct = 1.0f;
    g_vsum[t] = g_vsum[t] / ct;
}

// ---- 3: sparse conv via mma.sync bf16 3-term split ----
// CTA: 128 rows x 96 cols. 8 warps: warp_m = wid&3 (32 rows), warp_n = wid>>2 (48 cols).
__global__ __launch_bounds__(256)
void conv_mma_kernel(const int* __restrict__ nbr, int M) {
    extern __shared__ char smem[];
    int tid = threadIdx.x;
    int wid = tid >> 5;
    int lane = tid & 31;
    int mbase = blockIdx.x * CTM;

    int prow = tid >> 1;          // producer row 0..127
    int phalf = tid & 1;          // producer k-half (16 floats each)
    int warp_m = wid & 3;
    int warp_n = wid >> 2;
    int r0 = lane >> 2;
    int c4 = (lane & 3) << 2;     // byte offset of bf16 pair within 32B k16-block

    float acc[2][6][4];
#pragma unroll
    for (int mt = 0; mt < 2; ++mt)
#pragma unroll
        for (int nt = 0; nt < 6; ++nt)
#pragma unroll
            for (int q = 0; q < 4; ++q) acc[mt][nt][q] = 0.0f;

    // ---- produce stage 0 into buf 0 ----
    {
        int m = mbase + prow;
        int row = (m < M) ? nbr[(size_t)m * 27 + 0] : M;
        const float4* src = (const float4*)(g_vsum + (size_t)row * CIN + phalf * 16);
        char* ah = smem + (size_t)prow * ASTRIDE + phalf * 32;
        char* al = ah + APLANE;
#pragma unroll
        for (int i = 0; i < 4; ++i) {
            float4 v = src[i];
            float hx = __bfloat162float(__float2bfloat16(v.x));
            float hy = __bfloat162float(__float2bfloat16(v.y));
            float hz = __bfloat162float(__float2bfloat16(v.z));
            float hw = __bfloat162float(__float2bfloat16(v.w));
            uint2 H = make_uint2(pack_bf16(hx, hy), pack_bf16(hz, hw));
            uint2 L = make_uint2(pack_bf16(v.x - hx, v.y - hy), pack_bf16(v.z - hz, v.w - hw));
            *(uint2*)(ah + i * 8) = H;
            *(uint2*)(al + i * 8) = L;
        }
        const uint4* bsrc = (const uint4*)(g_wprep);
        char* bb = smem + 2 * APLANE;
#pragma unroll
        for (int p = 0; p < 3; ++p) {
            int idx = tid + p * 256;
            uint4 bv = bsrc[idx];
            int pl = idx / 384;
            int rem = idx - pl * 384;
            *(uint4*)(bb + pl * BPLANE + (rem >> 2) * ASTRIDE + (rem & 3) * 16) = bv;
        }
    }
    __syncthreads();

    for (int it = 0; it < NSTG; ++it) {
        int buf = it & 1;
        bool pf = (it + 1 < NSTG);
        float4 va[4];
        uint4 vb[3];
        if (pf) {
            int knext = (it + 1) / 6, chnext = (it + 1) - knext * 6;
            int m = mbase + prow;
            int row = (m < M) ? nbr[(size_t)m * 27 + knext] : M;
            const float4* src = (const float4*)(g_vsum + (size_t)row * CIN + chnext * 32 + phalf * 16);
#pragma unroll
            for (int i = 0; i < 4; ++i) va[i] = src[i];
            const uint4* bsrc = (const uint4*)(g_wprep + (size_t)(it + 1) * 2 * 3072);
#pragma unroll
            for (int p = 0; p < 3; ++p) vb[p] = bsrc[tid + p * 256];
        }

        // ---- consume buf ----
        {
            const char* base = smem + buf * STGB;
            const char* ahb = base;
            const char* alb = base + APLANE;
            const char* bhb = base + 2 * APLANE;
            const char* blb = bhb + BPLANE;
#pragma unroll
            for (int s = 0; s < 2; ++s) {
                int kb = s * 32 + c4;
                uint32_t Ah[2][4], Al[2][4], Bh[6][2], Bl[6][2];
#pragma unroll
                for (int mt = 0; mt < 2; ++mt) {
                    int roff = (warp_m * 32 + mt * 16 + r0) * ASTRIDE + kb;
                    Ah[mt][0] = *(const uint32_t*)(ahb + roff);
                    Ah[mt][1] = *(const uint32_t*)(ahb + roff + 8 * ASTRIDE);
                    Ah[mt][2] = *(const uint32_t*)(ahb + roff + 16);
                    Ah[mt][3] = *(const uint32_t*)(ahb + roff + 8 * ASTRIDE + 16);
                    Al[mt][0] = *(const uint32_t*)(alb + roff);
                    Al[mt][1] = *(const uint32_t*)(alb + roff + 8 * ASTRIDE);
                    Al[mt][2] = *(const uint32_t*)(alb + roff + 16);
                    Al[mt][3] = *(const uint32_t*)(alb + roff + 8 * ASTRIDE + 16);
                }
#pragma unroll
                for (int nt = 0; nt < 6; ++nt) {
                    int noff = (warp_n * 48 + nt * 8 + r0) * ASTRIDE + kb;
                    Bh[nt][0] = *(const uint32_t*)(bhb + noff);
                    Bh[nt][1] = *(const uint32_t*)(bhb + noff + 16);
                    Bl[nt][0] = *(const uint32_t*)(blb + noff);
                    Bl[nt][1] = *(const uint32_t*)(blb + noff + 16);
                }
#pragma unroll
                for (int nt = 0; nt < 6; ++nt) {
#pragma unroll
                    for (int mt = 0; mt < 2; ++mt) {
                        MMA_BF16(acc[mt][nt], Ah[mt], Bh[nt]);
                        MMA_BF16(acc[mt][nt], Al[mt], Bh[nt]);
                        MMA_BF16(acc[mt][nt], Ah[mt], Bl[nt]);
                    }
                }
            }
        }

        // ---- store prefetched stage into buf^1 ----
        if (pf) {
            char* stg = smem + (buf ^ 1) * STGB;
            char* ah = stg + (size_t)prow * ASTRIDE + phalf * 32;
            char* al = ah + APLANE;
#pragma unroll
            for (int i = 0; i < 4; ++i) {
                float4 v = va[i];
                float hx = __bfloat162float(__float2bfloat16(v.x));
                float hy = __bfloat162float(__float2bfloat16(v.y));
                float hz = __bfloat162float(__float2bfloat16(v.z));
                float hw = __bfloat162float(__float2bfloat16(v.w));
                uint2 H = make_uint2(pack_bf16(hx, hy), pack_bf16(hz, hw));
                uint2 L = make_uint2(pack_bf16(v.x - hx, v.y - hy), pack_bf16(v.z - hz, v.w - hw));
                *(uint2*)(ah + i * 8) = H;
                *(uint2*)(al + i * 8) = L;
            }
            char* bb = stg + 2 * APLANE;
#pragma unroll
            for (int p = 0; p < 3; ++p) {
                int idx = tid + p * 256;
                int pl = idx / 384;
                int rem = idx - pl * 384;
                *(uint4*)(bb + pl * BPLANE + (rem >> 2) * ASTRIDE + (rem & 3) * 16) = vb[p];
            }
        }
        __syncthreads();
    }

    // ---- epilogue ----
    int cc = (lane & 3) << 1;
#pragma unroll
    for (int mt = 0; mt < 2; ++mt) {
        int row = mbase + warp_m * 32 + mt * 16 + r0;
#pragma unroll
        for (int nt = 0; nt < 6; ++nt) {
            int col = warp_n * 48 + nt * 8 + cc;
            if (row < M)
                *(float2*)(g_acc + (size_t)row * HID + col) =
                    make_float2(acc[mt][nt][0], acc[mt][nt][1]);
            if (row + 8 < M)
                *(float2*)(g_acc + (size_t)(row + 8) * HID + col) =
                    make_float2(acc[mt][nt][2], acc[mt][nt][3]);
        }
    }
}

// ---- 4: BN statistics ----
__global__ void bnstats_kernel(int M) {
    int j = threadIdx.x % HID;
    int rs = threadIdx.x / HID;
    float s = 0.0f, q = 0.0f;
    for (int r = blockIdx.x * 4 + rs; r < M; r += gridDim.x * 4) {
        float v = g_acc[(size_t)r * HID + j];
        s += v;
        q += v * v;
    }
    __shared__ float sh[2][384];
    sh[0][threadIdx.x] = s;
    sh[1][threadIdx.x] = q;
    __syncthreads();
    if (threadIdx.x < HID) {
        s = sh[0][j] + sh[0][j + 96] + sh[0][j + 192] + sh[0][j + 288];
        q = sh[1][j] + sh[1][j + 96] + sh[1][j + 192] + sh[1][j + 288];
        atomicAdd(&g_bn[j], s);
        atomicAdd(&g_bn[HID + j], q);
    }
}

// ---- 5: BN scale/shift ----
__global__ void bnscale_kernel(const float* __restrict__ gamma,
                               const float* __restrict__ beta, int M) {
    int j = threadIdx.x;
    if (j >= HID) return;
    float inv = 1.0f / (float)M;
    float mu = g_bn[j] * inv;
    float var = g_bn[HID + j] * inv - mu * mu;
    if (var < 0.0f) var = 0.0f;
    float sc = gamma[j] * rsqrtf(var + EPSBN);
    g_ss[j] = sc;
    g_ss[HID + j] = beta[j] - mu * sc;
}

// ---- 6: BN apply + ReLU -> ypad ----
__global__ void ypad_kernel(int M) {
    long long t = (long long)blockIdx.x * blockDim.x + threadIdx.x;
    if (t >= (long long)(M + 1) * HID) return;
    int m = (int)(t / HID);
    int j = (int)(t - (long long)m * HID);
    float v = 0.0f;
    if (m < M) {
        v = g_acc[t] * g_ss[j] + g_ss[HID + j];
        v = v > 0.0f ? v : 0.0f;
    }
    g_ypad[t] = v;
}

// ---- 7: residual linear GEMM (fp32 SIMT) ----
__global__ __launch_bounds__(256, 2)
void linear_kernel(const float* __restrict__ hF, const float* __restrict__ qF,
                   const float* __restrict__ Wl, const float* __restrict__ bl,
                   float* __restrict__ out, int N) {
    __shared__ float As[2][TM * (KC + 1)];
    __shared__ float Bs[2][KC * HID];

    int tid = threadIdx.x;
    int nbase = blockIdx.x * TM;
    int tr = tid >> 4;
    int tc = tid & 15;

    float acc[8][6];
#pragma unroll
    for (int i = 0; i < 8; ++i)
#pragma unroll
        for (int p = 0; p < 6; ++p) acc[i][p] = 0.0f;

    {
#pragma unroll
        for (int i = 0; i < 8; ++i) {
            int idx = i * 256 + tid;
            int c = idx & (KC - 1), r = idx >> 4;
            int n = nbase + r;
            float v = 0.0f;
            if (n < N) v = hF[(size_t)n * HID + c];
            As[0][r * (KC + 1) + c] = v;
        }
#pragma unroll
        for (int i = 0; i < 6; ++i) {
            int idx = i * 256 + tid;
            Bs[0][idx] = Wl[idx];
        }
    }
    __syncthreads();
    int buf = 0;
#pragma unroll
    for (int ch = 0; ch < NCH; ++ch) {
        float ra[8], rb[6];
        if (ch < NCH - 1) {
            int cbase = (ch + 1) * KC;
#pragma unroll
            for (int i = 0; i < 8; ++i) {
                int idx = i * 256 + tid;
                int c = idx & (KC - 1), r = idx >> 4;
                int n = nbase + r;
                int col = cbase + c;
                float v = 0.0f;
                if (n < N)
                    v = (col < HID) ? hF[(size_t)n * HID + col]
                                    : qF[(size_t)n * HID + (col - HID)];
                ra[i] = v;
            }
#pragma unroll
            for (int i = 0; i < 6; ++i) {
                int idx = i * 256 + tid;
                rb[i] = Wl[(size_t)cbase * HID + idx];
            }
        }
        const float* Ab = &As[buf][0];
        const float* Bb = &Bs[buf][0];
#pragma unroll
        for (int c = 0; c < KC; ++c) {
            float a[8], b[6];
#pragma unroll
            for (int i = 0; i < 8; ++i) a[i] = Ab[(tr * 8 + i) * (KC + 1) + c];
#pragma unroll
            for (int p = 0; p < 6; ++p) b[p] = Bb[c * HID + tc * 6 + p];
#pragma unroll
            for (int i = 0; i < 8; ++i)
#pragma unroll
                for (int p = 0; p < 6; ++p) acc[i][p] += a[i] * b[p];
        }
        if (ch < NCH - 1) {
            int nb = buf ^ 1;
#pragma unroll
            for (int i = 0; i < 8; ++i) {
                int idx = i * 256 + tid;
                int c = idx & (KC - 1), r = idx >> 4;
                As[nb][r * (KC + 1) + c] = ra[i];
            }
#pragma unroll
            for (int i = 0; i < 6; ++i) Bs[nb][i * 256 + tid] = rb[i];
            __syncthreads();
            buf = nb;
        }
    }
#pragma unroll
    for (int i = 0; i < 8; ++i) {
        int n = nbase + tr * 8 + i;
        if (n < N) {
#pragma unroll
            for (int p = 0; p < 6; ++p)
                out[(size_t)n * HID + tc * 6 + p] = acc[i][p] + bl[tc * 6 + p];
        }
    }
}

// ---- 8: trilinear 8-corner gather ----
__global__ void trilinear_kernel(const float* __restrict__ cw, const int* __restrict__ cidx,
                                 float* __restrict__ out, int N) {
    long long t = (long long)blockIdx.x * blockDim.x + threadIdx.x;
    if (t >= (long long)N * HID) return;
    int n = (int)(t / HID);
    int j = (int)(t - (long long)n * HID);
    float s = out[t];
#pragma unroll
    for (int k = 0; k < 8; ++k) {
        int ci = cidx[(size_t)n * 8 + k];
        float w = cw[(size_t)n * 8 + k];
        s += w * g_ypad[(size_t)ci * HID + j];
    }
    out[t] = s;
}

extern "C" void kernel_launch(void* const* d_in, const int* in_sizes, int n_in,
                              void* d_out, int out_size) {
    const float* hF    = (const float*)d_in[0];
    const float* qF    = (const float*)d_in[1];
    const float* Wc    = (const float*)d_in[2];
    const float* gamma = (const float*)d_in[3];
    const float* beta  = (const float*)d_in[4];
    const float* Wl    = (const float*)d_in[5];
    const float* bl    = (const float*)d_in[6];
    const float* cw    = (const float*)d_in[7];
    const int*   seg   = (const int*)d_in[8];
    const int*   nbr   = (const int*)d_in[9];
    const int*   cidx  = (const int*)d_in[10];
    float* out = (float*)d_out;

    int N = in_sizes[8];
    int M = in_sizes[9] / 27;

    cudaFuncSetAttribute(conv_mma_kernel,
                         cudaFuncAttributeMaxDynamicSharedMemorySize, SMEM_CONV);

    void *pv, *pc, *pb;
    cudaGetSymbolAddress(&pv, g_vsum);
    cudaGetSymbolAddress(&pc, g_cnt);
    cudaGetSymbolAddress(&pb, g_bn);
    cudaMemsetAsync(pv, 0, (size_t)(M + 1) * CIN * sizeof(float), 0);
    cudaMemsetAsync(pc, 0, (size_t)M * sizeof(float), 0);
    cudaMemsetAsync(pb, 0, 2 * HID * sizeof(float), 0);

    prep_kernel<<<NSTG, 256>>>(Wc);

    long long nt;
    nt = (long long)N * CIN;
    scatter_kernel<<<(unsigned)((nt + 255) / 256), 256>>>(hF, qF, seg, N);

    nt = (long long)M * CIN;
    normalize_kernel<<<(unsigned)((nt + 255) / 256), 256>>>(M);

    conv_mma_kernel<<<(M + CTM - 1) / CTM, 256, SMEM_CONV>>>(nbr, M);

    bnstats_kernel<<<512, 384>>>(M);
    bnscale_kernel<<<1, HID>>>(gamma, beta, M);

    nt = (long long)(M + 1) * HID;
    ypad_kernel<<<(unsigned)((nt + 255) / 256), 256>>>(M);

    linear_kernel<<<(N + TM - 1) / TM, 256>>>(hF, qF, Wl, bl, out, N);

    nt = (long long)N * HID;
    trilinear_kernel<<<(unsigned)((nt + 255) / 256), 256>>>(cw, cidx, out, N);
}